// round 5
// baseline (speedup 1.0000x reference)
#include <cuda_runtime.h>
#include <cstdint>

#define NB 16
#define NS 196
#define NHEADS 8
#define NDH 64
#define NHID 512
#define NM (NB*NS)                       // 3136 rows for projections
#define BUF_ELEMS (NB*NHEADS*NS*NDH)     // 1,605,632 floats per buffer

__device__ float g_Q[BUF_ELEMS];
__device__ float g_K[BUF_ELEMS];
__device__ float g_V[BUF_ELEMS];
__device__ float g_G[BUF_ELEMS];

// ---- packed f32x2 helpers ----
__device__ __forceinline__ void fma2(unsigned long long& d,
                                     unsigned long long a,
                                     unsigned long long b) {
    asm("fma.rn.f32x2 %0, %1, %2, %0;" : "+l"(d) : "l"(a), "l"(b));
}
__device__ __forceinline__ void unpack2(unsigned long long v, float& lo, float& hi) {
    asm("mov.b64 {%0, %1}, %2;" : "=f"(lo), "=f"(hi) : "l"(v));
}

// ---- tf32 helpers ----
__device__ __forceinline__ float tf32_hi(float x) {
    return __uint_as_float(__float_as_uint(x) & 0xffffe000u);
}
__device__ __forceinline__ void mma_tf32(float* d, const uint32_t* a, const uint32_t* b) {
    asm volatile(
        "mma.sync.aligned.m16n8k8.row.col.f32.tf32.tf32.f32 "
        "{%0,%1,%2,%3}, {%4,%5,%6,%7}, {%8,%9}, {%0,%1,%2,%3};"
        : "+f"(d[0]), "+f"(d[1]), "+f"(d[2]), "+f"(d[3])
        : "r"(a[0]), "r"(a[1]), "r"(a[2]), "r"(a[3]), "r"(b[0]), "r"(b[1]));
}

// ---------------------------------------------------------------------------
// Kernel 1: fused QKVG projections via tf32 tensor-core MMA, 3xTF32 precision.
// y = x @ W + b, output [b,h,s,d].  Block: 128x128 tile, 256 thr (8 warps 2x4),
// warp tile 64x32, k-stage 16.  grid = (4, 25, 4).
// ---------------------------------------------------------------------------
#define PP 136   // smem pitch (floats): 136 % 32 == 8 -> conflict-free fragments

__global__ __launch_bounds__(256) void proj_kernel(
    const float* __restrict__ X,
    const float* __restrict__ W0, const float* __restrict__ b0,
    const float* __restrict__ W1, const float* __restrict__ b1,
    const float* __restrict__ W2, const float* __restrict__ b2,
    const float* __restrict__ W3, const float* __restrict__ b3)
{
    const float* W;
    const float* bias;
    float* out;
    switch (blockIdx.z) {
        case 0:  W = W0; bias = b0; out = g_Q; break;
        case 1:  W = W1; bias = b1; out = g_K; break;
        case 2:  W = W2; bias = b2; out = g_V; break;
        default: W = W3; bias = b3; out = g_G; break;
    }

    __shared__ float As_hi[16][PP];
    __shared__ float As_lo[16][PP];
    __shared__ float Bs_hi[16][PP];
    __shared__ float Bs_lo[16][PP];

    const int m0 = blockIdx.y * 128;
    const int n0 = blockIdx.x * 128;
    const int tid  = threadIdx.x;
    const int warp = tid >> 5;
    const int lane = tid & 31;
    const int wm = (warp >> 2) * 64;
    const int wn = (warp & 3) * 32;

    float acc[4][4][4];
#pragma unroll
    for (int i = 0; i < 4; ++i)
#pragma unroll
        for (int j = 0; j < 4; ++j)
#pragma unroll
            for (int v = 0; v < 4; ++v) acc[i][j][v] = 0.f;

    for (int k0 = 0; k0 < NHID; k0 += 16) {
        // ---- stage A (X[m0:m0+128, k0:k0+16]) transposed, split hi/lo ----
#pragma unroll
        for (int j = tid; j < 512; j += 256) {
            const int r  = j >> 2;          // 0..127 (m)
            const int c4 = (j & 3) * 4;     // 0,4,8,12 (k)
            float4 v = make_float4(0.f, 0.f, 0.f, 0.f);
            const int gm = m0 + r;
            if (gm < NM)
                v = *(const float4*)(X + (size_t)gm * NHID + k0 + c4);
            const float h0 = tf32_hi(v.x), h1 = tf32_hi(v.y),
                        h2 = tf32_hi(v.z), h3 = tf32_hi(v.w);
            As_hi[c4 + 0][r] = h0; As_lo[c4 + 0][r] = tf32_hi(v.x - h0);
            As_hi[c4 + 1][r] = h1; As_lo[c4 + 1][r] = tf32_hi(v.y - h1);
            As_hi[c4 + 2][r] = h2; As_lo[c4 + 2][r] = tf32_hi(v.z - h2);
            As_hi[c4 + 3][r] = h3; As_lo[c4 + 3][r] = tf32_hi(v.w - h3);
        }
        // ---- stage B (W[k0:k0+16, n0:n0+128]) split hi/lo ----
#pragma unroll
        for (int j = tid; j < 512; j += 256) {
            const int r  = j >> 5;          // 0..15 (k)
            const int c4 = (j & 31) * 4;    // 0..124 (n)
            const float4 v = *(const float4*)(W + (size_t)(k0 + r) * NHID + n0 + c4);
            float4 hi, lo;
            hi.x = tf32_hi(v.x); lo.x = tf32_hi(v.x - hi.x);
            hi.y = tf32_hi(v.y); lo.y = tf32_hi(v.y - hi.y);
            hi.z = tf32_hi(v.z); lo.z = tf32_hi(v.z - hi.z);
            hi.w = tf32_hi(v.w); lo.w = tf32_hi(v.w - hi.w);
            *(float4*)&Bs_hi[r][c4] = hi;
            *(float4*)&Bs_lo[r][c4] = lo;
        }
        __syncthreads();

#pragma unroll
        for (int ks = 0; ks < 16; ks += 8) {
            const int ca = ks + (lane & 3);
            const int ra = wm + (lane >> 2);
            uint32_t ah[4][4], al[4][4];
#pragma unroll
            for (int mt = 0; mt < 4; ++mt) {
                const int r = ra + mt * 16;
                ah[mt][0] = __float_as_uint(As_hi[ca][r]);
                ah[mt][1] = __float_as_uint(As_hi[ca][r + 8]);
                ah[mt][2] = __float_as_uint(As_hi[ca + 4][r]);
                ah[mt][3] = __float_as_uint(As_hi[ca + 4][r + 8]);
                al[mt][0] = __float_as_uint(As_lo[ca][r]);
                al[mt][1] = __float_as_uint(As_lo[ca][r + 8]);
                al[mt][2] = __float_as_uint(As_lo[ca + 4][r]);
                al[mt][3] = __float_as_uint(As_lo[ca + 4][r + 8]);
            }
            const int rb = ks + (lane & 3);
            const int cb = wn + (lane >> 2);
            uint32_t bh[4][2], bl[4][2];
#pragma unroll
            for (int nt = 0; nt < 4; ++nt) {
                bh[nt][0] = __float_as_uint(Bs_hi[rb][cb + nt * 8]);
                bh[nt][1] = __float_as_uint(Bs_hi[rb + 4][cb + nt * 8]);
                bl[nt][0] = __float_as_uint(Bs_lo[rb][cb + nt * 8]);
                bl[nt][1] = __float_as_uint(Bs_lo[rb + 4][cb + nt * 8]);
            }
#pragma unroll
            for (int mt = 0; mt < 4; ++mt)
#pragma unroll
                for (int nt = 0; nt < 4; ++nt) {
                    mma_tf32(acc[mt][nt], ah[mt], bh[nt]);
                    mma_tf32(acc[mt][nt], al[mt], bh[nt]);
                    mma_tf32(acc[mt][nt], ah[mt], bl[nt]);
                }
        }
        __syncthreads();
    }

    // ---- epilogue: bias + scatter to [b,h,s,d] ----
#pragma unroll
    for (int mt = 0; mt < 4; ++mt) {
#pragma unroll
        for (int nt = 0; nt < 4; ++nt) {
#pragma unroll
            for (int v = 0; v < 4; ++v) {
                const int row = wm + mt * 16 + (lane >> 2) + (v >> 1) * 8;
                const int col = wn + nt * 8 + 2 * (lane & 3) + (v & 1);
                const int m = m0 + row;
                if (m >= NM) continue;
                const int n = n0 + col;
                const int bI = m / NS;
                const int sI = m - bI * NS;
                const int h = n >> 6, d = n & 63;
                out[(((size_t)bI * NHEADS + h) * NS + sI) * NDH + d] =
                    acc[mt][nt][v] + bias[n];
            }
        }
    }
}

// ---------------------------------------------------------------------------
// Kernel 2: attention with geometric bias.
// Phase 0: sc[qi,k] = scale*q.K + mask, K staged in smem chunks (once per blk).
// Phase 1: sc[qi,k] += g.rpe  (DRAM stream, f32x2 FMA, 2 shfls per 8 k's).
// Phase 2: softmax + probs write.  Phase 3: ctx = probs @ V.
// ---------------------------------------------------------------------------
#define TQ 14
#define SP 200
#define KCH 49
#define KPP 68   // K smem pitch (16B aligned)

__global__ __launch_bounds__(256) void attn_kernel(
    const float* __restrict__ rpe, const float* __restrict__ mask,
    float* __restrict__ out_ctx, float* __restrict__ out_probs,
    int write_probs)
{
    __shared__ float Ksm[KCH][KPP];
    __shared__ float qsm[TQ * NDH];
    __shared__ float gsm[TQ * NDH];
    __shared__ float sc[TQ * SP];
    __shared__ float msk[NS];

    const int q0 = blockIdx.x * TQ;
    const int h  = blockIdx.y;
    const int b  = blockIdx.z;
    const int bh = b * NHEADS + h;
    const int tid  = threadIdx.x;
    const int warp = tid >> 5;
    const int lane = tid & 31;

    // ---- stage q, g, mask ----
    {
        const float* Qb = g_Q + ((size_t)bh * NS + q0) * NDH;
        const float* Gb = g_G + ((size_t)bh * NS + q0) * NDH;
        for (int j = tid; j < TQ * NDH; j += 256) {
            qsm[j] = Qb[j] * 0.125f;   // 1/sqrt(64)
            gsm[j] = Gb[j];
        }
        if (tid < NS) msk[tid] = mask[b * NS + tid];
    }
    __syncthreads();

    // ---- phase 0: sc = scale*q.K + mask (K chunked through smem) ----
    const float* Kbh = g_K + (size_t)bh * NS * NDH;
    for (int c = 0; c < 4; ++c) {
        const int k0c = c * KCH;
        for (int j = tid; j < KCH * 16; j += 256) {
            const int r = j >> 4, seg = j & 15;
            *(float4*)&Ksm[r][seg * 4] =
                *(const float4*)(Kbh + (size_t)(k0c + r) * NDH + seg * 4);
        }
        __syncthreads();
        for (int qi = warp; qi < TQ; qi += 8) {
#pragma unroll
            for (int base = 0; base < KCH; base += 32) {
                const int kl = base + lane;
                if (kl < KCH) {
                    float a = 0.f;
#pragma unroll
                    for (int seg = 0; seg < 16; ++seg) {
                        const float4 qv = *(const float4*)&qsm[qi * NDH + seg * 4];
                        const float4 kv = *(const float4*)&Ksm[kl][seg * 4];
                        a += qv.x * kv.x + qv.y * kv.y + qv.z * kv.z + qv.w * kv.w;
                    }
                    sc[qi * SP + k0c + kl] = a + msk[k0c + kl];
                }
            }
        }
        __syncthreads();
    }

    // ---- phase 1: sc += g.rpe (pure DRAM stream) ----
    const int kk  = lane >> 2;   // 0..7: k within 8-group
    const int sub = lane & 3;    // 0..3: d-group
    const float* rb = rpe + ((size_t)bh * NS + q0) * (size_t)NS * NDH;

    const int NTASK = TQ * 25;
    for (int task = warp; task < NTASK; task += 8) {
        const int qi = task / 25;
        const int kg = task - qi * 25;
        const int k  = kg * 8 + kk;
        const bool valid = (k < NS);
        const float* rrow = rb + ((size_t)qi * NS + k) * NDH;

        unsigned long long acc2 = 0ull;
#pragma unroll
        for (int j = 0; j < 4; ++j) {
            const int qd = (sub + 4 * j) * 4;
            if (valid) {
                const ulonglong2 rv = *(const ulonglong2*)(rrow + qd);
                const ulonglong2 gv = *(const ulonglong2*)&gsm[qi * NDH + qd];
                fma2(acc2, gv.x, rv.x);
                fma2(acc2, gv.y, rv.y);
            }
        }
        float lo, hi;
        unpack2(acc2, lo, hi);
        float a = lo + hi;
        a += __shfl_xor_sync(0xffffffffu, a, 1);
        a += __shfl_xor_sync(0xffffffffu, a, 2);
        if (sub == 0 && valid) sc[qi * SP + k] += a;
    }
    __syncthreads();

    // ---- phase 2: softmax per row + probs write ----
    for (int qi = warp; qi < TQ; qi += 8) {
        float m = -1e30f;
        for (int j = lane; j < NS; j += 32) m = fmaxf(m, sc[qi * SP + j]);
#pragma unroll
        for (int o = 16; o; o >>= 1) m = fmaxf(m, __shfl_xor_sync(0xffffffffu, m, o));
        float sum = 0.f;
        for (int j = lane; j < NS; j += 32) {
            const float e = __expf(sc[qi * SP + j] - m);
            sc[qi * SP + j] = e;
            sum += e;
        }
#pragma unroll
        for (int o = 16; o; o >>= 1) sum += __shfl_xor_sync(0xffffffffu, sum, o);
        const float inv = 1.0f / sum;
        const size_t pb = ((size_t)bh * NS + q0 + qi) * NS;
        for (int j = lane; j < NS; j += 32) {
            const float p = sc[qi * SP + j] * inv;
            sc[qi * SP + j] = p;
            if (write_probs) out_probs[pb + j] = p;
        }
    }
    __syncthreads();

    // ---- phase 3: ctx = probs @ V ----
    const int g = tid >> 6;      // 0..3
    const int d = tid & 63;
    const int nq = (g < 2) ? 4 : 3;
    const float* Vb = g_V + (size_t)bh * NS * NDH;

    float acc[4] = {0.f, 0.f, 0.f, 0.f};
#pragma unroll 4
    for (int k = 0; k < NS; ++k) {
        const float v = Vb[(size_t)k * NDH + d];
#pragma unroll
        for (int t = 0; t < 4; ++t)
            if (t < nq) acc[t] += sc[(g + 4 * t) * SP + k] * v;
    }
#pragma unroll
    for (int t = 0; t < 4; ++t) {
        if (t >= nq) break;
        const int qi = g + 4 * t;
        out_ctx[(((size_t)b * NS + q0 + qi) * NHEADS + h) * NDH + d] = acc[t];
    }
}

// ---------------------------------------------------------------------------
extern "C" void kernel_launch(void* const* d_in, const int* in_sizes, int n_in,
                              void* d_out, int out_size)
{
    const float* hidden = (const float*)d_in[0];
    const float* rpe    = (const float*)d_in[1];
    const float* mask   = (const float*)d_in[2];
    const float* Wq = (const float*)d_in[3];
    const float* bq = (const float*)d_in[4];
    const float* Wk = (const float*)d_in[5];
    const float* bk = (const float*)d_in[6];
    const float* Wv = (const float*)d_in[7];
    const float* bv = (const float*)d_in[8];
    const float* Wg = (const float*)d_in[9];
    const float* bg = (const float*)d_in[10];

    float* out = (float*)d_out;
    const size_t ctx_elems   = (size_t)NB * NS * NHID;
    const size_t probs_elems = (size_t)NB * NHEADS * NS * NS;
    const int write_probs = ((size_t)out_size >= ctx_elems + probs_elems) ? 1 : 0;
    float* out_probs = out + ctx_elems;

    proj_kernel<<<dim3(4, 25, 4), 256>>>(hidden, Wq, bq, Wk, bk, Wv, bv, Wg, bg);
    attn_kernel<<<dim3(NS / TQ, NHEADS, NB), 256>>>(
        rpe, mask, out, out_probs, write_probs);
}

// round 9
// speedup vs baseline: 2.4671x; 2.4671x over previous
#include <cuda_runtime.h>
#include <cstdint>

#define NB 16
#define NS 196
#define NHEADS 8
#define NDH 64
#define NHID 512
#define NM (NB*NS)                       // 3136 rows for projections
#define BUF_ELEMS (NB*NHEADS*NS*NDH)     // 1,605,632 floats per buffer

__device__ float g_Q[BUF_ELEMS];
__device__ float g_K[BUF_ELEMS];
__device__ float g_V[BUF_ELEMS];
__device__ float g_G[BUF_ELEMS];

// ---- tf32 helpers ----
__device__ __forceinline__ float tf32_hi(float x) {
    return __uint_as_float(__float_as_uint(x) & 0xffffe000u);
}
__device__ __forceinline__ void mma_tf32(float* d, const uint32_t* a, const uint32_t* b) {
    asm volatile(
        "mma.sync.aligned.m16n8k8.row.col.f32.tf32.tf32.f32 "
        "{%0,%1,%2,%3}, {%4,%5,%6,%7}, {%8,%9}, {%0,%1,%2,%3};"
        : "+f"(d[0]), "+f"(d[1]), "+f"(d[2]), "+f"(d[3])
        : "r"(a[0]), "r"(a[1]), "r"(a[2]), "r"(a[3]), "r"(b[0]), "r"(b[1]));
}

// ---------------------------------------------------------------------------
// Kernel 1: fused QKVG projections via tf32 tensor-core MMA, 3xTF32 precision.
// y = x @ W + b, output [b,h,s,d].  Block: 128x128 tile, 256 thr (8 warps 2x4),
// warp tile 64x32, k-stage 16.  grid = (4, 25, 4).   (validated: rel_err ~8e-6)
// ---------------------------------------------------------------------------
#define PP 136   // smem pitch (floats): 136 % 32 == 8 -> conflict-free fragments

__global__ __launch_bounds__(256) void proj_kernel(
    const float* __restrict__ X,
    const float* __restrict__ W0, const float* __restrict__ b0,
    const float* __restrict__ W1, const float* __restrict__ b1,
    const float* __restrict__ W2, const float* __restrict__ b2,
    const float* __restrict__ W3, const float* __restrict__ b3)
{
    const float* W;
    const float* bias;
    float* out;
    switch (blockIdx.z) {
        case 0:  W = W0; bias = b0; out = g_Q; break;
        case 1:  W = W1; bias = b1; out = g_K; break;
        case 2:  W = W2; bias = b2; out = g_V; break;
        default: W = W3; bias = b3; out = g_G; break;
    }

    __shared__ float As_hi[16][PP];
    __shared__ float As_lo[16][PP];
    __shared__ float Bs_hi[16][PP];
    __shared__ float Bs_lo[16][PP];

    const int m0 = blockIdx.y * 128;
    const int n0 = blockIdx.x * 128;
    const int tid  = threadIdx.x;
    const int warp = tid >> 5;
    const int lane = tid & 31;
    const int wm = (warp >> 2) * 64;
    const int wn = (warp & 3) * 32;

    float acc[4][4][4];
#pragma unroll
    for (int i = 0; i < 4; ++i)
#pragma unroll
        for (int j = 0; j < 4; ++j)
#pragma unroll
            for (int v = 0; v < 4; ++v) acc[i][j][v] = 0.f;

    for (int k0 = 0; k0 < NHID; k0 += 16) {
        // ---- stage A (X[m0:m0+128, k0:k0+16]) transposed, split hi/lo ----
#pragma unroll
        for (int j = tid; j < 512; j += 256) {
            const int r  = j >> 2;          // 0..127 (m)
            const int c4 = (j & 3) * 4;     // 0,4,8,12 (k)
            float4 v = make_float4(0.f, 0.f, 0.f, 0.f);
            const int gm = m0 + r;
            if (gm < NM)
                v = *(const float4*)(X + (size_t)gm * NHID + k0 + c4);
            const float h0 = tf32_hi(v.x), h1 = tf32_hi(v.y),
                        h2 = tf32_hi(v.z), h3 = tf32_hi(v.w);
            As_hi[c4 + 0][r] = h0; As_lo[c4 + 0][r] = tf32_hi(v.x - h0);
            As_hi[c4 + 1][r] = h1; As_lo[c4 + 1][r] = tf32_hi(v.y - h1);
            As_hi[c4 + 2][r] = h2; As_lo[c4 + 2][r] = tf32_hi(v.z - h2);
            As_hi[c4 + 3][r] = h3; As_lo[c4 + 3][r] = tf32_hi(v.w - h3);
        }
        // ---- stage B (W[k0:k0+16, n0:n0+128]) split hi/lo ----
#pragma unroll
        for (int j = tid; j < 512; j += 256) {
            const int r  = j >> 5;          // 0..15 (k)
            const int c4 = (j & 31) * 4;    // 0..124 (n)
            const float4 v = *(const float4*)(W + (size_t)(k0 + r) * NHID + n0 + c4);
            float4 hi, lo;
            hi.x = tf32_hi(v.x); lo.x = tf32_hi(v.x - hi.x);
            hi.y = tf32_hi(v.y); lo.y = tf32_hi(v.y - hi.y);
            hi.z = tf32_hi(v.z); lo.z = tf32_hi(v.z - hi.z);
            hi.w = tf32_hi(v.w); lo.w = tf32_hi(v.w - hi.w);
            *(float4*)&Bs_hi[r][c4] = hi;
            *(float4*)&Bs_lo[r][c4] = lo;
        }
        __syncthreads();

#pragma unroll
        for (int ks = 0; ks < 16; ks += 8) {
            const int ca = ks + (lane & 3);
            const int ra = wm + (lane >> 2);
            uint32_t ah[4][4], al[4][4];
#pragma unroll
            for (int mt = 0; mt < 4; ++mt) {
                const int r = ra + mt * 16;
                ah[mt][0] = __float_as_uint(As_hi[ca][r]);
                ah[mt][1] = __float_as_uint(As_hi[ca][r + 8]);
                ah[mt][2] = __float_as_uint(As_hi[ca + 4][r]);
                ah[mt][3] = __float_as_uint(As_hi[ca + 4][r + 8]);
                al[mt][0] = __float_as_uint(As_lo[ca][r]);
                al[mt][1] = __float_as_uint(As_lo[ca][r + 8]);
                al[mt][2] = __float_as_uint(As_lo[ca + 4][r]);
                al[mt][3] = __float_as_uint(As_lo[ca + 4][r + 8]);
            }
            const int rb = ks + (lane & 3);
            const int cb = wn + (lane >> 2);
            uint32_t bh[4][2], bl[4][2];
#pragma unroll
            for (int nt = 0; nt < 4; ++nt) {
                bh[nt][0] = __float_as_uint(Bs_hi[rb][cb + nt * 8]);
                bh[nt][1] = __float_as_uint(Bs_hi[rb + 4][cb + nt * 8]);
                bl[nt][0] = __float_as_uint(Bs_lo[rb][cb + nt * 8]);
                bl[nt][1] = __float_as_uint(Bs_lo[rb + 4][cb + nt * 8]);
            }
#pragma unroll
            for (int mt = 0; mt < 4; ++mt)
#pragma unroll
                for (int nt = 0; nt < 4; ++nt) {
                    mma_tf32(acc[mt][nt], ah[mt], bh[nt]);
                    mma_tf32(acc[mt][nt], al[mt], bh[nt]);
                    mma_tf32(acc[mt][nt], ah[mt], bl[nt]);
                }
        }
        __syncthreads();
    }

    // ---- epilogue: bias + scatter to [b,h,s,d] ----
#pragma unroll
    for (int mt = 0; mt < 4; ++mt) {
#pragma unroll
        for (int nt = 0; nt < 4; ++nt) {
#pragma unroll
            for (int v = 0; v < 4; ++v) {
                const int row = wm + mt * 16 + (lane >> 2) + (v >> 1) * 8;
                const int col = wn + nt * 8 + 2 * (lane & 3) + (v & 1);
                const int m = m0 + row;
                if (m >= NM) continue;
                const int n = n0 + col;
                const int bI = m / NS;
                const int sI = m - bI * NS;
                const int h = n >> 6, d = n & 63;
                out[(((size_t)bI * NHEADS + h) * NS + sI) * NDH + d] =
                    acc[mt][nt][v] + bias[n];
            }
        }
    }
}

// ---------------------------------------------------------------------------
// Kernel 2: attention with geometric bias.
// Lane mapping (phases 0 & 1): warp = 4 k's, 8 lanes per k, full-128B lines.
// Phase 0: sc = scale*q.K + mask  (k-outer: each K row read once per block,
//          reused for all 14 queries from registers).
// Phase 1: sc += g.rpe  (pure DRAM stream, qi-outer).
// Phase 2: softmax + probs write.  Phase 3: ctx = probs @ V.
// __launch_bounds__(256,5) caps regs at 51 -> >=5 blocks/SM (lesson of R5).
// ---------------------------------------------------------------------------
#define TQ 14
#define SP 200
#define NG 49    // 196 / 4 k-groups

__global__ __launch_bounds__(256, 5) void attn_kernel(
    const float* __restrict__ rpe, const float* __restrict__ mask,
    float* __restrict__ out_ctx, float* __restrict__ out_probs,
    int write_probs)
{
    __shared__ float qsm[TQ * NDH];   // pre-scaled q
    __shared__ float gsm[TQ * NDH];
    __shared__ float sc[TQ * SP];
    __shared__ float msk[NS];

    const int q0 = blockIdx.x * TQ;
    const int h  = blockIdx.y;
    const int b  = blockIdx.z;
    const int bh = b * NHEADS + h;
    const int tid  = threadIdx.x;
    const int warp = tid >> 5;
    const int lane = tid & 31;
    const int kk  = lane >> 3;   // 0..3: k within 4-group
    const int sub = lane & 7;    // 0..7: 16B segment within row half

    // ---- stage q, g, mask ----
    {
        const float* Qb = g_Q + ((size_t)bh * NS + q0) * NDH;
        const float* Gb = g_G + ((size_t)bh * NS + q0) * NDH;
        for (int j = tid; j < TQ * NDH; j += 256) {
            qsm[j] = Qb[j] * 0.125f;   // 1/sqrt(64)
            gsm[j] = Gb[j];
        }
        if (tid < NS) msk[tid] = mask[b * NS + tid];
    }
    __syncthreads();

    // ---- phase 0: sc = scale*q.K + mask (K rows read once, reused 14x) ----
    const float* Kbh = g_K + (size_t)bh * NS * NDH;
    for (int grp = warp; grp < NG; grp += 8) {
        const int k = grp * 4 + kk;          // always < 196
        const float* krow = Kbh + (size_t)k * NDH;
        const float4 kv0 = *(const float4*)(krow + sub * 4);
        const float4 kv1 = *(const float4*)(krow + (sub + 8) * 4);
        for (int qi = 0; qi < TQ; ++qi) {
            const float4 q0v = *(const float4*)&qsm[qi * NDH + sub * 4];
            const float4 q1v = *(const float4*)&qsm[qi * NDH + (sub + 8) * 4];
            float a = q0v.x * kv0.x + q0v.y * kv0.y + q0v.z * kv0.z + q0v.w * kv0.w
                    + q1v.x * kv1.x + q1v.y * kv1.y + q1v.z * kv1.z + q1v.w * kv1.w;
            a += __shfl_xor_sync(0xffffffffu, a, 1);
            a += __shfl_xor_sync(0xffffffffu, a, 2);
            a += __shfl_xor_sync(0xffffffffu, a, 4);
            if (sub == 0) sc[qi * SP + k] = a + msk[k];
        }
    }
    __syncthreads();

    // ---- phase 1: sc += g.rpe (pure DRAM stream) ----
    const float* rb = rpe + ((size_t)bh * NS + q0) * (size_t)NS * NDH;
    for (int qi = 0; qi < TQ; ++qi) {
        const float4 g0v = *(const float4*)&gsm[qi * NDH + sub * 4];
        const float4 g1v = *(const float4*)&gsm[qi * NDH + (sub + 8) * 4];
        const float* rq = rb + (size_t)qi * NS * NDH;
#pragma unroll 2
        for (int grp = warp; grp < NG; grp += 8) {
            const int k = grp * 4 + kk;
            const float* rrow = rq + (size_t)k * NDH;
            const float4 rv0 = *(const float4*)(rrow + sub * 4);
            const float4 rv1 = *(const float4*)(rrow + (sub + 8) * 4);
            float a = g0v.x * rv0.x + g0v.y * rv0.y + g0v.z * rv0.z + g0v.w * rv0.w
                    + g1v.x * rv1.x + g1v.y * rv1.y + g1v.z * rv1.z + g1v.w * rv1.w;
            a += __shfl_xor_sync(0xffffffffu, a, 1);
            a += __shfl_xor_sync(0xffffffffu, a, 2);
            a += __shfl_xor_sync(0xffffffffu, a, 4);
            if (sub == 0) sc[qi * SP + k] += a;
        }
    }
    __syncthreads();

    // ---- phase 2: softmax per row + probs write ----
    for (int qi = warp; qi < TQ; qi += 8) {
        float m = -1e30f;
        for (int j = lane; j < NS; j += 32) m = fmaxf(m, sc[qi * SP + j]);
#pragma unroll
        for (int o = 16; o; o >>= 1) m = fmaxf(m, __shfl_xor_sync(0xffffffffu, m, o));
        float sum = 0.f;
        for (int j = lane; j < NS; j += 32) {
            const float e = __expf(sc[qi * SP + j] - m);
            sc[qi * SP + j] = e;
            sum += e;
        }
#pragma unroll
        for (int o = 16; o; o >>= 1) sum += __shfl_xor_sync(0xffffffffu, sum, o);
        const float inv = 1.0f / sum;
        const size_t pb = ((size_t)bh * NS + q0 + qi) * NS;
        for (int j = lane; j < NS; j += 32) {
            const float p = sc[qi * SP + j] * inv;
            sc[qi * SP + j] = p;
            if (write_probs) out_probs[pb + j] = p;
        }
    }
    __syncthreads();

    // ---- phase 3: ctx = probs @ V ----
    const int g = tid >> 6;      // 0..3
    const int d = tid & 63;
    const int nq = (g < 2) ? 4 : 3;
    const float* Vb = g_V + (size_t)bh * NS * NDH;

    float acc[4] = {0.f, 0.f, 0.f, 0.f};
#pragma unroll 4
    for (int k = 0; k < NS; ++k) {
        const float v = Vb[(size_t)k * NDH + d];
#pragma unroll
        for (int t = 0; t < 4; ++t)
            if (t < nq) acc[t] += sc[(g + 4 * t) * SP + k] * v;
    }
#pragma unroll
    for (int t = 0; t < 4; ++t) {
        if (t >= nq) break;
        const int qi = g + 4 * t;
        out_ctx[(((size_t)b * NS + q0 + qi) * NHEADS + h) * NDH + d] = acc[t];
    }
}

// ---------------------------------------------------------------------------
extern "C" void kernel_launch(void* const* d_in, const int* in_sizes, int n_in,
                              void* d_out, int out_size)
{
    const float* hidden = (const float*)d_in[0];
    const float* rpe    = (const float*)d_in[1];
    const float* mask   = (const float*)d_in[2];
    const float* Wq = (const float*)d_in[3];
    const float* bq = (const float*)d_in[4];
    const float* Wk = (const float*)d_in[5];
    const float* bk = (const float*)d_in[6];
    const float* Wv = (const float*)d_in[7];
    const float* bv = (const float*)d_in[8];
    const float* Wg = (const float*)d_in[9];
    const float* bg = (const float*)d_in[10];

    float* out = (float*)d_out;
    const size_t ctx_elems   = (size_t)NB * NS * NHID;
    const size_t probs_elems = (size_t)NB * NHEADS * NS * NS;
    const int write_probs = ((size_t)out_size >= ctx_elems + probs_elems) ? 1 : 0;
    float* out_probs = out + ctx_elems;

    proj_kernel<<<dim3(4, 25, 4), 256>>>(hidden, Wq, bq, Wk, bk, Wv, bv, Wg, bg);
    attn_kernel<<<dim3(NS / TQ, NHEADS, NB), 256>>>(
        rpe, mask, out, out_probs, write_probs);
}

// round 11
// speedup vs baseline: 2.8429x; 1.1523x over previous
#include <cuda_runtime.h>
#include <cstdint>

#define NB 16
#define NS 196
#define NHEADS 8
#define NDH 64
#define NHID 512
#define NM (NB*NS)                       // 3136 rows for projections
#define BUF_ELEMS (NB*NHEADS*NS*NDH)     // 1,605,632 floats per buffer

__device__ float g_Q[BUF_ELEMS];
__device__ float g_K[BUF_ELEMS];
__device__ float g_V[BUF_ELEMS];
__device__ float g_G[BUF_ELEMS];

// ---- tf32 helpers ----
__device__ __forceinline__ float tf32_hi(float x) {
    return __uint_as_float(__float_as_uint(x) & 0xffffe000u);
}
__device__ __forceinline__ void mma_tf32(float* d, const uint32_t* a, const uint32_t* b) {
    asm volatile(
        "mma.sync.aligned.m16n8k8.row.col.f32.tf32.tf32.f32 "
        "{%0,%1,%2,%3}, {%4,%5,%6,%7}, {%8,%9}, {%0,%1,%2,%3};"
        : "+f"(d[0]), "+f"(d[1]), "+f"(d[2]), "+f"(d[3])
        : "r"(a[0]), "r"(a[1]), "r"(a[2]), "r"(a[3]), "r"(b[0]), "r"(b[1]));
}

// ---------------------------------------------------------------------------
// Kernel 1: fused QKVG projections via tf32 tensor-core MMA, 3xTF32 precision.
// (validated: rel_err ~8e-6; unchanged from R9)
// ---------------------------------------------------------------------------
#define PP 136   // smem pitch (floats): 136 % 32 == 8 -> conflict-free fragments

__global__ __launch_bounds__(256) void proj_kernel(
    const float* __restrict__ X,
    const float* __restrict__ W0, const float* __restrict__ b0,
    const float* __restrict__ W1, const float* __restrict__ b1,
    const float* __restrict__ W2, const float* __restrict__ b2,
    const float* __restrict__ W3, const float* __restrict__ b3)
{
    const float* W;
    const float* bias;
    float* out;
    switch (blockIdx.z) {
        case 0:  W = W0; bias = b0; out = g_Q; break;
        case 1:  W = W1; bias = b1; out = g_K; break;
        case 2:  W = W2; bias = b2; out = g_V; break;
        default: W = W3; bias = b3; out = g_G; break;
    }

    __shared__ float As_hi[16][PP];
    __shared__ float As_lo[16][PP];
    __shared__ float Bs_hi[16][PP];
    __shared__ float Bs_lo[16][PP];

    const int m0 = blockIdx.y * 128;
    const int n0 = blockIdx.x * 128;
    const int tid  = threadIdx.x;
    const int warp = tid >> 5;
    const int lane = tid & 31;
    const int wm = (warp >> 2) * 64;
    const int wn = (warp & 3) * 32;

    float acc[4][4][4];
#pragma unroll
    for (int i = 0; i < 4; ++i)
#pragma unroll
        for (int j = 0; j < 4; ++j)
#pragma unroll
            for (int v = 0; v < 4; ++v) acc[i][j][v] = 0.f;

    for (int k0 = 0; k0 < NHID; k0 += 16) {
#pragma unroll
        for (int j = tid; j < 512; j += 256) {
            const int r  = j >> 2;
            const int c4 = (j & 3) * 4;
            float4 v = make_float4(0.f, 0.f, 0.f, 0.f);
            const int gm = m0 + r;
            if (gm < NM)
                v = *(const float4*)(X + (size_t)gm * NHID + k0 + c4);
            const float h0 = tf32_hi(v.x), h1 = tf32_hi(v.y),
                        h2 = tf32_hi(v.z), h3 = tf32_hi(v.w);
            As_hi[c4 + 0][r] = h0; As_lo[c4 + 0][r] = tf32_hi(v.x - h0);
            As_hi[c4 + 1][r] = h1; As_lo[c4 + 1][r] = tf32_hi(v.y - h1);
            As_hi[c4 + 2][r] = h2; As_lo[c4 + 2][r] = tf32_hi(v.z - h2);
            As_hi[c4 + 3][r] = h3; As_lo[c4 + 3][r] = tf32_hi(v.w - h3);
        }
#pragma unroll
        for (int j = tid; j < 512; j += 256) {
            const int r  = j >> 5;
            const int c4 = (j & 31) * 4;
            const float4 v = *(const float4*)(W + (size_t)(k0 + r) * NHID + n0 + c4);
            float4 hi, lo;
            hi.x = tf32_hi(v.x); lo.x = tf32_hi(v.x - hi.x);
            hi.y = tf32_hi(v.y); lo.y = tf32_hi(v.y - hi.y);
            hi.z = tf32_hi(v.z); lo.z = tf32_hi(v.z - hi.z);
            hi.w = tf32_hi(v.w); lo.w = tf32_hi(v.w - hi.w);
            *(float4*)&Bs_hi[r][c4] = hi;
            *(float4*)&Bs_lo[r][c4] = lo;
        }
        __syncthreads();

#pragma unroll
        for (int ks = 0; ks < 16; ks += 8) {
            const int ca = ks + (lane & 3);
            const int ra = wm + (lane >> 2);
            uint32_t ah[4][4], al[4][4];
#pragma unroll
            for (int mt = 0; mt < 4; ++mt) {
                const int r = ra + mt * 16;
                ah[mt][0] = __float_as_uint(As_hi[ca][r]);
                ah[mt][1] = __float_as_uint(As_hi[ca][r + 8]);
                ah[mt][2] = __float_as_uint(As_hi[ca + 4][r]);
                ah[mt][3] = __float_as_uint(As_hi[ca + 4][r + 8]);
                al[mt][0] = __float_as_uint(As_lo[ca][r]);
                al[mt][1] = __float_as_uint(As_lo[ca][r + 8]);
                al[mt][2] = __float_as_uint(As_lo[ca + 4][r]);
                al[mt][3] = __float_as_uint(As_lo[ca + 4][r + 8]);
            }
            const int rb = ks + (lane & 3);
            const int cb = wn + (lane >> 2);
            uint32_t bh[4][2], bl[4][2];
#pragma unroll
            for (int nt = 0; nt < 4; ++nt) {
                bh[nt][0] = __float_as_uint(Bs_hi[rb][cb + nt * 8]);
                bh[nt][1] = __float_as_uint(Bs_hi[rb + 4][cb + nt * 8]);
                bl[nt][0] = __float_as_uint(Bs_lo[rb][cb + nt * 8]);
                bl[nt][1] = __float_as_uint(Bs_lo[rb + 4][cb + nt * 8]);
            }
#pragma unroll
            for (int mt = 0; mt < 4; ++mt)
#pragma unroll
                for (int nt = 0; nt < 4; ++nt) {
                    mma_tf32(acc[mt][nt], ah[mt], bh[nt]);
                    mma_tf32(acc[mt][nt], al[mt], bh[nt]);
                    mma_tf32(acc[mt][nt], ah[mt], bl[nt]);
                }
        }
        __syncthreads();
    }

#pragma unroll
    for (int mt = 0; mt < 4; ++mt) {
#pragma unroll
        for (int nt = 0; nt < 4; ++nt) {
#pragma unroll
            for (int v = 0; v < 4; ++v) {
                const int row = wm + mt * 16 + (lane >> 2) + (v >> 1) * 8;
                const int col = wn + nt * 8 + 2 * (lane & 3) + (v & 1);
                const int m = m0 + row;
                if (m >= NM) continue;
                const int n = n0 + col;
                const int bI = m / NS;
                const int sI = m - bI * NS;
                const int h = n >> 6, d = n & 63;
                out[(((size_t)bI * NHEADS + h) * NS + sI) * NDH + d] =
                    acc[mt][nt][v] + bias[n];
            }
        }
    }
}

// ---------------------------------------------------------------------------
// Kernel 2: attention with geometric bias.
// Lane mapping: warp = 4 k's, 8 lanes per k (full-128B-line wavefronts).
// Phase 1 streams rpe as a flat task list (t = qi*49 + grp, 686 tasks),
// TWO tasks per iteration with all 4 LDG.128 front-batched -> loads stay in
// flight during the shuffle-reduce chains (fix for R9 duty-cycle stall).
// ---------------------------------------------------------------------------
#define TQ 14
#define SP 200
#define NG 49            // 196 / 4 k-groups
#define NT (TQ * NG)     // 686 flat tasks

__global__ __launch_bounds__(256, 5) void attn_kernel(
    const float* __restrict__ rpe, const float* __restrict__ mask,
    float* __restrict__ out_ctx, float* __restrict__ out_probs,
    int write_probs)
{
    __shared__ float qsm[TQ * NDH];   // pre-scaled q
    __shared__ float gsm[TQ * NDH];
    __shared__ float sc[TQ * SP];
    __shared__ float msk[NS];

    const int q0 = blockIdx.x * TQ;
    const int h  = blockIdx.y;
    const int b  = blockIdx.z;
    const int bh = b * NHEADS + h;
    const int tid  = threadIdx.x;
    const int warp = tid >> 5;
    const int lane = tid & 31;
    const int kk  = lane >> 3;   // 0..3: k within 4-group
    const int sub = lane & 7;    // 0..7: 16B segment within row

    // ---- stage q, g, mask ----
    {
        const float* Qb = g_Q + ((size_t)bh * NS + q0) * NDH;
        const float* Gb = g_G + ((size_t)bh * NS + q0) * NDH;
        for (int j = tid; j < TQ * NDH; j += 256) {
            qsm[j] = Qb[j] * 0.125f;   // 1/sqrt(64)
            gsm[j] = Gb[j];
        }
        if (tid < NS) msk[tid] = mask[b * NS + tid];
    }
    __syncthreads();

    // ---- phase 0: sc = scale*q.K + mask (K rows read once, reused 14x) ----
    const float* Kbh = g_K + (size_t)bh * NS * NDH;
    for (int grp = warp; grp < NG; grp += 8) {
        const int k = grp * 4 + kk;          // always < 196
        const float* krow = Kbh + (size_t)k * NDH;
        const float4 kv0 = *(const float4*)(krow + sub * 4);
        const float4 kv1 = *(const float4*)(krow + (sub + 8) * 4);
        for (int qi = 0; qi < TQ; ++qi) {
            const float4 q0v = *(const float4*)&qsm[qi * NDH + sub * 4];
            const float4 q1v = *(const float4*)&qsm[qi * NDH + (sub + 8) * 4];
            float a = q0v.x * kv0.x + q0v.y * kv0.y + q0v.z * kv0.z + q0v.w * kv0.w
                    + q1v.x * kv1.x + q1v.y * kv1.y + q1v.z * kv1.z + q1v.w * kv1.w;
            a += __shfl_xor_sync(0xffffffffu, a, 1);
            a += __shfl_xor_sync(0xffffffffu, a, 2);
            a += __shfl_xor_sync(0xffffffffu, a, 4);
            if (sub == 0) sc[qi * SP + k] = a + msk[k];
        }
    }
    __syncthreads();

    // ---- phase 1: sc += g.rpe, 2 tasks per iteration, loads front-batched ----
    const float* rb = rpe + ((size_t)bh * NS + q0) * (size_t)NS * NDH;
    for (int t0 = warp; t0 < NT; t0 += 16) {
        // task A indices
        const int qa = t0 / NG;
        const int ka = (t0 - qa * NG) * 4 + kk;
        const float* ra = rb + ((size_t)qa * NS + ka) * NDH;
        // task B indices (may be out of range)
        const int t1 = t0 + 8;
        const bool vb = (t1 < NT);
        const int qb = vb ? (t1 / NG) : 0;
        const int kb = vb ? ((t1 - qb * NG) * 4 + kk) : 0;
        const float* rbp = rb + ((size_t)qb * NS + kb) * NDH;

        // front-batched loads: 4 independent LDG.128 + 4 LDS.128
        const float4 ra0 = *(const float4*)(ra + sub * 4);
        const float4 ra1 = *(const float4*)(ra + (sub + 8) * 4);
        float4 rb0 = make_float4(0.f, 0.f, 0.f, 0.f);
        float4 rb1 = make_float4(0.f, 0.f, 0.f, 0.f);
        if (vb) {
            rb0 = *(const float4*)(rbp + sub * 4);
            rb1 = *(const float4*)(rbp + (sub + 8) * 4);
        }
        const float4 ga0 = *(const float4*)&gsm[qa * NDH + sub * 4];
        const float4 ga1 = *(const float4*)&gsm[qa * NDH + (sub + 8) * 4];
        const float4 gb0 = *(const float4*)&gsm[qb * NDH + sub * 4];
        const float4 gb1 = *(const float4*)&gsm[qb * NDH + (sub + 8) * 4];

        // reduce A
        float a = ga0.x * ra0.x + ga0.y * ra0.y + ga0.z * ra0.z + ga0.w * ra0.w
                + ga1.x * ra1.x + ga1.y * ra1.y + ga1.z * ra1.z + ga1.w * ra1.w;
        a += __shfl_xor_sync(0xffffffffu, a, 1);
        a += __shfl_xor_sync(0xffffffffu, a, 2);
        a += __shfl_xor_sync(0xffffffffu, a, 4);
        if (sub == 0) sc[qa * SP + ka] += a;

        // reduce B
        if (vb) {
            float c = gb0.x * rb0.x + gb0.y * rb0.y + gb0.z * rb0.z + gb0.w * rb0.w
                    + gb1.x * rb1.x + gb1.y * rb1.y + gb1.z * rb1.z + gb1.w * rb1.w;
            c += __shfl_xor_sync(0xffffffffu, c, 1);
            c += __shfl_xor_sync(0xffffffffu, c, 2);
            c += __shfl_xor_sync(0xffffffffu, c, 4);
            if (sub == 0) sc[qb * SP + kb] += c;
        }
    }
    __syncthreads();

    // ---- phase 2: softmax per row + probs write ----
    for (int qi = warp; qi < TQ; qi += 8) {
        float m = -1e30f;
        for (int j = lane; j < NS; j += 32) m = fmaxf(m, sc[qi * SP + j]);
#pragma unroll
        for (int o = 16; o; o >>= 1) m = fmaxf(m, __shfl_xor_sync(0xffffffffu, m, o));
        float sum = 0.f;
        for (int j = lane; j < NS; j += 32) {
            const float e = __expf(sc[qi * SP + j] - m);
            sc[qi * SP + j] = e;
            sum += e;
        }
#pragma unroll
        for (int o = 16; o; o >>= 1) sum += __shfl_xor_sync(0xffffffffu, sum, o);
        const float inv = 1.0f / sum;
        const size_t pb = ((size_t)bh * NS + q0 + qi) * NS;
        for (int j = lane; j < NS; j += 32) {
            const float p = sc[qi * SP + j] * inv;
            sc[qi * SP + j] = p;
            if (write_probs) out_probs[pb + j] = p;
        }
    }
    __syncthreads();

    // ---- phase 3: ctx = probs @ V ----
    const int g = tid >> 6;      // 0..3
    const int d = tid & 63;
    const int nq = (g < 2) ? 4 : 3;
    const float* Vb = g_V + (size_t)bh * NS * NDH;

    float acc[4] = {0.f, 0.f, 0.f, 0.f};
#pragma unroll 4
    for (int k = 0; k < NS; ++k) {
        const float v = Vb[(size_t)k * NDH + d];
#pragma unroll
        for (int t = 0; t < 4; ++t)
            if (t < nq) acc[t] += sc[(g + 4 * t) * SP + k] * v;
    }
#pragma unroll
    for (int t = 0; t < 4; ++t) {
        if (t >= nq) break;
        const int qi = g + 4 * t;
        out_ctx[(((size_t)b * NS + q0 + qi) * NHEADS + h) * NDH + d] = acc[t];
    }
}

// ---------------------------------------------------------------------------
extern "C" void kernel_launch(void* const* d_in, const int* in_sizes, int n_in,
                              void* d_out, int out_size)
{
    const float* hidden = (const float*)d_in[0];
    const float* rpe    = (const float*)d_in[1];
    const float* mask   = (const float*)d_in[2];
    const float* Wq = (const float*)d_in[3];
    const float* bq = (const float*)d_in[4];
    const float* Wk = (const float*)d_in[5];
    const float* bk = (const float*)d_in[6];
    const float* Wv = (const float*)d_in[7];
    const float* bv = (const float*)d_in[8];
    const float* Wg = (const float*)d_in[9];
    const float* bg = (const float*)d_in[10];

    float* out = (float*)d_out;
    const size_t ctx_elems   = (size_t)NB * NS * NHID;
    const size_t probs_elems = (size_t)NB * NHEADS * NS * NS;
    const int write_probs = ((size_t)out_size >= ctx_elems + probs_elems) ? 1 : 0;
    float* out_probs = out + ctx_elems;

    proj_kernel<<<dim3(4, 25, 4), 256>>>(hidden, Wq, bq, Wk, bk, Wv, bv, Wg, bg);
    attn_kernel<<<dim3(NS / TQ, NHEADS, NB), 256>>>(
        rpe, mask, out, out_probs, write_probs);
}